// round 4
// baseline (speedup 1.0000x reference)
#include <cuda_runtime.h>
#include <cuda_bf16.h>

#define BB 4
#define CC 64
#define DWC 128
#define HH 256
#define WW 256
#define HWP (HH*WW)
#define HWP2 (HWP/2)
#define EPSF 1e-6f

typedef unsigned long long u64;
typedef unsigned int u32;

// packed f32x2 helpers
#define PACK2(d, s)   asm("mov.b64 %0, {%1, %1};" : "=l"(d) : "f"(s))
#define FMA2(c, a, b) asm("fma.rn.f32x2 %0, %1, %2, %0;" : "+l"(c) : "l"(a), "l"(b))
#define ADD2(d, a, b) asm("add.rn.f32x2 %0, %1, %2;" : "=l"(d) : "l"(a), "l"(b))
#define MUL2(d, a, b) asm("mul.rn.f32x2 %0, %1, %2;" : "=l"(d) : "l"(a), "l"(b))
#define UNPACK2(lo, hi, v) asm("mov.b64 {%0, %1}, %2;" : "=f"(lo), "=f"(hi) : "l"(v))

static __device__ __forceinline__ u32 cvt_pair_bf16(u64 v) {
    float lo, hi; UNPACK2(lo, hi, v);
    u32 r;
    asm("cvt.rn.bf16x2.f32 %0, %1, %2;" : "=r"(r) : "f"(hi), "f"(lo));
    return r;
}
static __device__ __forceinline__ float2 bf16pair_to_f2(u32 v) {
    __nv_bfloat162 b = *reinterpret_cast<__nv_bfloat162*>(&v);
    return __bfloat1622float2(b);
}
static __device__ __forceinline__ float topk_gate(const float* probs, int b, int& be) {
    float best = probs[b*3]; be = 0;
    #pragma unroll
    for (int e = 1; e < 3; e++) {
        float p = probs[b*3+e];
        if (p > best) { best = p; be = e; }
    }
    return best * 2.0f;  // gate * SCALING
}

// ---------------- device scratch ----------------
__device__ u32 g_u[BB][DWC][HWP2];       // conv1 out, bf16 pairs (64 MB)
__device__ u32 g_t[BB][CC][HWP2];        // gated out, bf16 pairs (32 MB)
__device__ float g_poolpart[BB][CC][32]; // deterministic pool partials

// ---------------- K1: LN1 + conv1 (64->128), TP=128 pix, dup-packed weights ----------------
#define TP1 128
#define XS1 132
#define WD1 130   // u64 stride

__global__ __launch_bounds__(256) void k1_ln_conv1(
    const float* __restrict__ inp, const float* __restrict__ probs,
    const float* __restrict__ w1, const float* __restrict__ la1, const float* __restrict__ lb1,
    const float* __restrict__ ln1w, const float* __restrict__ ln1b, const float* __restrict__ b1)
{
    extern __shared__ char smraw[];
    u64*   wd   = (u64*)smraw;                 // [64][130] dup-packed weff1^T
    float* xs   = (float*)(wd + 64*WD1);       // [64][132]
    float* psum = xs + 64*XS1;                 // 256
    float* psq  = psum + 256;                  // 256
    float* mu   = psq + 256;                   // 128
    float* rstd = mu + 128;                    // 128

    int b = blockIdx.y;
    int pixbase = blockIdx.x * TP1;
    int t = threadIdx.x;
    int be; float g = topk_gate(probs, b, be);

    const float* X = inp + (size_t)b*CC*HWP + pixbase;
    int pix = t & 127;
    int crow = t >> 7;
    float s = 0.f, sq = 0.f;
    #pragma unroll
    for (int i = 0; i < 32; i++) {
        int c = crow + 2*i;
        float v = X[(size_t)c*HWP + pix];
        xs[c*XS1 + pix] = v; s += v; sq += v*v;
    }
    psum[crow*128+pix] = s; psq[crow*128+pix] = sq;

    // effective conv1 weights, transposed + dup-packed
    for (int idx = t; idx < DWC*CC; idx += 256) {
        int o = idx >> 6, i = idx & 63;
        float acc = 0.f;
        #pragma unroll
        for (int r = 0; r < 4; r++)
            acc += lb1[(be*DWC+o)*4+r] * la1[(be*4+r)*CC+i];
        float w = w1[idx] + g*acc;
        u64 wp; PACK2(wp, w);
        wd[i*WD1 + o] = wp;
    }
    __syncthreads();
    if (t < 128) {
        float m = (psum[t]+psum[128+t]) * (1.f/CC);
        float var = (psq[t]+psq[128+t]) * (1.f/CC) - m*m;
        mu[t] = m; rstd[t] = rsqrtf(var + EPSF);
    }
    __syncthreads();
    #pragma unroll
    for (int i = 0; i < 32; i++) {
        int c = crow + 2*i;
        xs[c*XS1+pix] = (xs[c*XS1+pix]-mu[pix])*rstd[pix]*ln1w[c] + ln1b[c];
    }
    __syncthreads();

    // GEMM: 8 oc x 8 pix (4 pairs) per thread, FFMA2 with preduped weights
    int oc0 = (t >> 4) * 8;
    int p0  = (t & 15) * 8;
    u64 acc[8][4];
    #pragma unroll
    for (int o = 0; o < 8; o++)
        #pragma unroll
        for (int p = 0; p < 4; p++) acc[o][p] = 0ULL;

    #pragma unroll 2
    for (int k = 0; k < CC; k++) {
        const u64* xr = (const u64*)(xs + k*XS1 + p0);
        ulonglong2 xa = *(const ulonglong2*)xr;
        ulonglong2 xb = *(const ulonglong2*)(xr+2);
        u64 xv[4] = {xa.x, xa.y, xb.x, xb.y};
        const ulonglong2* wr = (const ulonglong2*)(wd + k*WD1 + oc0);
        ulonglong2 w0 = wr[0], w1v = wr[1], w2v = wr[2], w3v = wr[3];
        u64 wp[8] = {w0.x,w0.y,w1v.x,w1v.y,w2v.x,w2v.y,w3v.x,w3v.y};
        #pragma unroll
        for (int o = 0; o < 8; o++)
            #pragma unroll
            for (int p = 0; p < 4; p++)
                FMA2(acc[o][p], wp[o], xv[p]);
    }
    int upix = (pixbase + p0) >> 1;
    #pragma unroll
    for (int o = 0; o < 8; o++) {
        int oc = oc0 + o;
        u64 bp; PACK2(bp, b1[oc]);
        u32 v[4];
        #pragma unroll
        for (int p = 0; p < 4; p++) {
            u64 r; ADD2(r, acc[o][p], bp);
            v[p] = cvt_pair_bf16(r);
        }
        *(uint4*)&g_u[b][oc][upix] = make_uint4(v[0], v[1], v[2], v[3]);
    }
}

// ---------------- K2: depthwise 3x3 + SimpleGate + pool partials (bf16 io) ----------------
__global__ __launch_bounds__(256) void k2_dw_gate_pool(
    const float* __restrict__ probs,
    const float* __restrict__ w2, const float* __restrict__ la2, const float* __restrict__ lb2,
    const float* __restrict__ b2)
{
    __shared__ float u0[10*258];
    __shared__ float u1[10*258];
    __shared__ float wsm[18];
    __shared__ float redbuf[8];
    int b = blockIdx.z, j = blockIdx.y;
    int r0 = blockIdx.x * 8;
    int t = threadIdx.x;
    int be; float g = topk_gate(probs, b, be);

    // 18 effective dw weights (channels j, j+64) by threads 0..17
    if (t < 18) {
        int ch = (t < 9) ? j : (j + CC);
        int kk = t % 9, kh = kk / 3, kw = kk % 3;
        float s = 0.f;
        #pragma unroll
        for (int r = 0; r < 12; r++)
            s += lb2[(be*384 + ch*3 + kh)*12 + r] * la2[(be*12+r)*3 + kw];
        wsm[t] = w2[ch*9 + kk] + g*s;
    }

    const u32* U0 = g_u[b][j];
    const u32* U1 = g_u[b][j+CC];
    for (int idx = t; idx < 10*128; idx += 256) {
        int rr = idx >> 7, cp = idx & 127;
        int row = r0 - 1 + rr;
        float2 v0 = make_float2(0.f, 0.f), v1 = v0;
        if (row >= 0 && row < HH) {
            v0 = bf16pair_to_f2(U0[row*128 + cp]);
            v1 = bf16pair_to_f2(U1[row*128 + cp]);
        }
        u0[rr*258 + 1 + 2*cp] = v0.x; u0[rr*258 + 2 + 2*cp] = v0.y;
        u1[rr*258 + 1 + 2*cp] = v1.x; u1[rr*258 + 2 + 2*cp] = v1.y;
    }
    if (t < 10) { u0[t*258] = 0.f; u1[t*258] = 0.f; }
    else if (t < 20) { int rr = t-10; u0[rr*258+257] = 0.f; u1[rr*258+257] = 0.f; }
    __syncthreads();

    float wa[9], wb[9];
    #pragma unroll
    for (int i = 0; i < 9; i++) { wa[i] = wsm[i]; wb[i] = wsm[9+i]; }
    float biasA = b2[j], biasB = b2[j+CC];

    int cp = t & 127, rg = t >> 7;
    int c0 = 2*cp;  // smem col of left output; taps c0..c0+3 cover both outputs
    float lsum = 0.f;
    #pragma unroll
    for (int ii = 0; ii < 4; ii++) {
        int orow = rg*4 + ii;            // 0..7 within tile
        float a0 = biasA, a1 = biasA, c0v = biasB, c1v = biasB;
        #pragma unroll
        for (int kh = 0; kh < 3; kh++) {
            const float* r0p = u0 + (orow+kh)*258 + c0;
            const float* r1p = u1 + (orow+kh)*258 + c0;
            float2 x01 = *(const float2*)r0p;
            float2 x23 = *(const float2*)(r0p+2);
            float2 y01 = *(const float2*)r1p;
            float2 y23 = *(const float2*)(r1p+2);
            a0 = fmaf(wa[kh*3+0], x01.x, a0); a0 = fmaf(wa[kh*3+1], x01.y, a0); a0 = fmaf(wa[kh*3+2], x23.x, a0);
            a1 = fmaf(wa[kh*3+0], x01.y, a1); a1 = fmaf(wa[kh*3+1], x23.x, a1); a1 = fmaf(wa[kh*3+2], x23.y, a1);
            c0v = fmaf(wb[kh*3+0], y01.x, c0v); c0v = fmaf(wb[kh*3+1], y01.y, c0v); c0v = fmaf(wb[kh*3+2], y23.x, c0v);
            c1v = fmaf(wb[kh*3+0], y01.y, c1v); c1v = fmaf(wb[kh*3+1], y23.x, c1v); c1v = fmaf(wb[kh*3+2], y23.y, c1v);
        }
        float p0v = a0 * c0v, p1v = a1 * c1v;
        u64 pp; asm("mov.b64 %0, {%1, %2};" : "=l"(pp) : "f"(p0v), "f"(p1v));
        g_t[b][j][(r0+orow)*128 + cp] = cvt_pair_bf16(pp);
        lsum += p0v + p1v;
    }
    #pragma unroll
    for (int off = 16; off > 0; off >>= 1) lsum += __shfl_down_sync(0xffffffffu, lsum, off);
    if ((t & 31) == 0) redbuf[t >> 5] = lsum;
    __syncthreads();
    if (t == 0) {
        float tot = 0.f;
        #pragma unroll
        for (int i = 0; i < 8; i++) tot += redbuf[i];
        g_poolpart[b][j][blockIdx.x] = tot;
    }
}

// ---------------- K4: sca + x*sca -> conv3 -> y -> LN2 -> conv4 -> gate -> conv5 -> out ----------------
#define TP4 128
#define SA 132    // bufA stride
#define SW 68     // w3s/w5s stride
#define SW4 132   // w4s stride

__global__ __launch_bounds__(256) void k4_final(
    const float* __restrict__ inp, const float* __restrict__ probs,
    const float* __restrict__ wsca, const float* __restrict__ bsca,
    const float* __restrict__ lasca, const float* __restrict__ lbsca,
    const float* __restrict__ w3, const float* __restrict__ b3,
    const float* __restrict__ la3, const float* __restrict__ lb3,
    const float* __restrict__ w4, const float* __restrict__ b4,
    const float* __restrict__ la4, const float* __restrict__ lb4,
    const float* __restrict__ w5, const float* __restrict__ b5,
    const float* __restrict__ la5, const float* __restrict__ lb5,
    const float* __restrict__ ln2w, const float* __restrict__ ln2b,
    const float* __restrict__ beta, const float* __restrict__ gamma,
    float* __restrict__ out)
{
    extern __shared__ float sm[];
    float* bufA = sm;                // 64*132
    float* w3s  = bufA + CC*SA;      // 64*68  [k][oc]
    float* w5s  = w3s + CC*SW;       // 64*68
    float* w4s  = w5s + CC*SW;       // 64*132 [k][oc]
    float* mu   = w4s + CC*SW4;      // 128
    float* rstd = mu + 128;          // 128
    float* redS = rstd + 128;        // 256
    float* redQ = redS + 256;        // 256
    float* scas = redQ + 256;        // 64
    float* pl   = scas + 64;         // 64

    int b = blockIdx.y;
    int pixbase = blockIdx.x * TP4;
    int t = threadIdx.x;
    int be; float g = topk_gate(probs, b, be);

    // effective weights (transposed) + pool sums
    for (int idx = t; idx < CC*CC; idx += 256) {
        int o = idx >> 6, i = idx & 63;
        float s3 = 0.f, s5 = 0.f;
        #pragma unroll
        for (int r = 0; r < 4; r++) {
            s3 += lb3[(be*CC+o)*4+r] * la3[(be*4+r)*CC+i];
            s5 += lb5[(be*CC+o)*4+r] * la5[(be*4+r)*CC+i];
        }
        w3s[i*SW+o] = w3[idx] + g*s3;
        w5s[i*SW+o] = w5[idx] + g*s5;
    }
    for (int idx = t; idx < DWC*CC; idx += 256) {
        int o = idx >> 6, i = idx & 63;
        float s4 = 0.f;
        #pragma unroll
        for (int r = 0; r < 4; r++)
            s4 += lb4[(be*DWC+o)*4+r] * la4[(be*4+r)*CC+i];
        w4s[i*SW4+o] = w4[idx] + g*s4;
    }
    if (t < CC) {
        float s = 0.f;
        #pragma unroll
        for (int p = 0; p < 32; p++) s += g_poolpart[b][t][p];
        pl[t] = s;
    }
    __syncthreads();
    if (t < CC) {
        float acc = 0.f;
        #pragma unroll 8
        for (int i = 0; i < CC; i++) {
            float s = 0.f;
            #pragma unroll
            for (int r = 0; r < 4; r++)
                s += lbsca[(be*CC+t)*4+r] * lasca[(be*4+r)*CC+i];
            acc += (wsca[t*CC+i] + g*s) * pl[i];
        }
        scas[t] = bsca[t] + acc * (1.f/HWP);
    }
    __syncthreads();

    // bufA = t * sca (bf16 pairs -> fp32)
    int prbase = pixbase >> 1;
    for (int idx = t; idx < CC*(TP4/2); idx += 256) {
        int c = idx >> 6, pr = idx & 63;
        float2 f = bf16pair_to_f2(g_t[b][c][prbase + pr]);
        float sc = scas[c];
        bufA[c*SA + 2*pr]   = f.x * sc;
        bufA[c*SA + 2*pr+1] = f.y * sc;
    }
    __syncthreads();

    int g4 = t >> 4, p16 = t & 15;
    int p0 = p16 * 8;
    int oc0 = g4 * 4;   // conv3/conv5 output channels
    int oc4 = g4 * 8;   // conv4 output channels

    // ---- conv3 ----
    u64 a3[4][4];
    #pragma unroll
    for (int o = 0; o < 4; o++)
        #pragma unroll
        for (int p = 0; p < 4; p++) a3[o][p] = 0ULL;
    #pragma unroll 2
    for (int k = 0; k < CC; k++) {
        const u64* xr = (const u64*)(bufA + k*SA + p0);
        ulonglong2 xa = *(const ulonglong2*)xr;
        ulonglong2 xb = *(const ulonglong2*)(xr+2);
        u64 xv[4] = {xa.x, xa.y, xb.x, xb.y};
        float4 wv = *(const float4*)(w3s + k*SW + oc0);
        u64 wp[4];
        PACK2(wp[0], wv.x); PACK2(wp[1], wv.y); PACK2(wp[2], wv.z); PACK2(wp[3], wv.w);
        #pragma unroll
        for (int o = 0; o < 4; o++)
            #pragma unroll
            for (int p = 0; p < 4; p++)
                FMA2(a3[o][p], wp[o], xv[p]);
    }
    __syncthreads();  // conv3 reads of bufA done

    // y = inp + (conv3+b3)*beta  -> regs + bufA
    float yreg[4][8];
    #pragma unroll
    for (int o = 0; o < 4; o++) {
        int oc = oc0 + o;
        const float* IP = inp + ((size_t)(b*CC+oc))*HWP + pixbase + p0;
        float4 i0 = *(const float4*)IP;
        float4 i1 = *(const float4*)(IP+4);
        float iv[8] = {i0.x,i0.y,i0.z,i0.w,i1.x,i1.y,i1.z,i1.w};
        float bb = b3[oc], bt = beta[oc];
        #pragma unroll
        for (int pr = 0; pr < 4; pr++) {
            float lo, hi; UNPACK2(lo, hi, a3[o][pr]);
            float y0 = iv[2*pr]   + (lo+bb)*bt;
            float y1 = iv[2*pr+1] + (hi+bb)*bt;
            yreg[o][2*pr] = y0; yreg[o][2*pr+1] = y1;
            *(float2*)(bufA + oc*SA + p0 + 2*pr) = make_float2(y0, y1);
        }
    }
    __syncthreads();

    // LN2 stats
    {
        int pp = t >> 1, q = t & 1;
        float s = 0.f, sq = 0.f;
        #pragma unroll
        for (int c = 0; c < 32; c++) {
            float v = bufA[(q*32+c)*SA + pp];
            s += v; sq += v*v;
        }
        redS[q*128+pp] = s; redQ[q*128+pp] = sq;
    }
    __syncthreads();
    if (t < 128) {
        float s  = redS[t]+redS[128+t];
        float sq = redQ[t]+redQ[128+t];
        float m = s * (1.f/CC);
        float var = sq * (1.f/CC) - m*m;
        mu[t] = m; rstd[t] = rsqrtf(var + EPSF);
    }
    __syncthreads();
    for (int idx = t; idx < CC*TP4; idx += 256) {
        int c = idx >> 7, pix = idx & 127;
        bufA[c*SA+pix] = (bufA[c*SA+pix]-mu[pix])*rstd[pix]*ln2w[c] + ln2b[c];
    }
    __syncthreads();

    // ---- conv4 (64->128) ----
    u64 a4[8][4];
    #pragma unroll
    for (int o = 0; o < 8; o++)
        #pragma unroll
        for (int p = 0; p < 4; p++) a4[o][p] = 0ULL;
    #pragma unroll 2
    for (int k = 0; k < CC; k++) {
        const u64* xr = (const u64*)(bufA + k*SA + p0);
        ulonglong2 xa = *(const ulonglong2*)xr;
        ulonglong2 xb = *(const ulonglong2*)(xr+2);
        u64 xv[4] = {xa.x, xa.y, xb.x, xb.y};
        const float4* wr = (const float4*)(w4s + k*SW4 + oc4);
        float4 w0 = wr[0], w1v = wr[1];
        float ws[8] = {w0.x,w0.y,w0.z,w0.w,w1v.x,w1v.y,w1v.z,w1v.w};
        u64 wp[8];
        #pragma unroll
        for (int o = 0; o < 8; o++) PACK2(wp[o], ws[o]);
        #pragma unroll
        for (int o = 0; o < 8; o++)
            #pragma unroll
            for (int p = 0; p < 4; p++)
                FMA2(a4[o][p], wp[o], xv[p]);
    }
    __syncthreads();  // conv4 reads done

    // SimpleGate into bufA
    if (oc4 >= CC) {
        #pragma unroll
        for (int o = 0; o < 8; o++) {
            int oc = oc4 + o;
            u64 bp; PACK2(bp, b4[oc]);
            #pragma unroll
            for (int pr = 0; pr < 4; pr++) {
                u64 r; ADD2(r, a4[o][pr], bp);
                *(u64*)(bufA + (oc-CC)*SA + p0 + 2*pr) = r;
            }
        }
    }
    __syncthreads();
    if (oc4 < CC) {
        #pragma unroll
        for (int o = 0; o < 8; o++) {
            int oc = oc4 + o;
            u64 bp; PACK2(bp, b4[oc]);
            #pragma unroll
            for (int pr = 0; pr < 4; pr++) {
                u64 up = *(u64*)(bufA + oc*SA + p0 + 2*pr);
                u64 r; ADD2(r, a4[o][pr], bp);
                u64 prod; MUL2(prod, r, up);
                *(u64*)(bufA + oc*SA + p0 + 2*pr) = prod;
            }
        }
    }
    __syncthreads();

    // ---- conv5 + final residual ----
    u64 a5[4][4];
    #pragma unroll
    for (int o = 0; o < 4; o++)
        #pragma unroll
        for (int p = 0; p < 4; p++) a5[o][p] = 0ULL;
    #pragma unroll 2
    for (int k = 0; k < CC; k++) {
        const u64* xr = (const u64*)(bufA + k*SA + p0);
        ulonglong2 xa = *(const ulonglong2*)xr;
        ulonglong2 xb = *(const ulonglong2*)(xr+2);
        u64 xv[4] = {xa.x, xa.y, xb.x, xb.y};
        float4 wv = *(const float4*)(w5s + k*SW + oc0);
        u64 wp[4];
        PACK2(wp[0], wv.x); PACK2(wp[1], wv.y); PACK2(wp[2], wv.z); PACK2(wp[3], wv.w);
        #pragma unroll
        for (int o = 0; o < 4; o++)
            #pragma unroll
            for (int p = 0; p < 4; p++)
                FMA2(a5[o][p], wp[o], xv[p]);
    }
    #pragma unroll
    for (int o = 0; o < 4; o++) {
        int oc = oc0 + o;
        float bb = b5[oc], gm = gamma[oc];
        float* OP = out + ((size_t)(b*CC+oc))*HWP + pixbase + p0;
        float ov[8];
        #pragma unroll
        for (int pr = 0; pr < 4; pr++) {
            float lo, hi; UNPACK2(lo, hi, a5[o][pr]);
            ov[2*pr]   = yreg[o][2*pr]   + (lo+bb)*gm;
            ov[2*pr+1] = yreg[o][2*pr+1] + (hi+bb)*gm;
        }
        *(float4*)OP     = make_float4(ov[0],ov[1],ov[2],ov[3]);
        *(float4*)(OP+4) = make_float4(ov[4],ov[5],ov[6],ov[7]);
    }
}

// ---------------- launch ----------------
extern "C" void kernel_launch(void* const* d_in, const int* in_sizes, int n_in,
                              void* d_out, int out_size)
{
    const float* inp   = (const float*)d_in[0];
    const float* probs = (const float*)d_in[1];
    const float* ln1w  = (const float*)d_in[2];
    const float* ln1b  = (const float*)d_in[3];
    const float* ln2w  = (const float*)d_in[4];
    const float* ln2b  = (const float*)d_in[5];
    const float* w1    = (const float*)d_in[6];
    const float* b1    = (const float*)d_in[7];
    const float* la1   = (const float*)d_in[8];
    const float* lb1   = (const float*)d_in[9];
    const float* w2    = (const float*)d_in[10];
    const float* b2    = (const float*)d_in[11];
    const float* la2   = (const float*)d_in[12];
    const float* lb2   = (const float*)d_in[13];
    const float* wsca  = (const float*)d_in[14];
    const float* bsca  = (const float*)d_in[15];
    const float* la_s  = (const float*)d_in[16];
    const float* lb_s  = (const float*)d_in[17];
    const float* w3    = (const float*)d_in[18];
    const float* b3    = (const float*)d_in[19];
    const float* la3   = (const float*)d_in[20];
    const float* lb3   = (const float*)d_in[21];
    const float* w4    = (const float*)d_in[22];
    const float* b4    = (const float*)d_in[23];
    const float* la4   = (const float*)d_in[24];
    const float* lb4   = (const float*)d_in[25];
    const float* w5    = (const float*)d_in[26];
    const float* b5    = (const float*)d_in[27];
    const float* la5   = (const float*)d_in[28];
    const float* lb5   = (const float*)d_in[29];
    const float* beta  = (const float*)d_in[30];
    const float* gamma = (const float*)d_in[31];
    float* out = (float*)d_out;

    const int smem1 = 64*WD1*8 + (64*XS1 + 256 + 256 + 128 + 128) * (int)sizeof(float);
    const int smem4 = (CC*SA + CC*SW*2 + CC*SW4 + 128*2 + 256*2 + 64 + 64) * (int)sizeof(float);
    cudaFuncSetAttribute(k1_ln_conv1, cudaFuncAttributeMaxDynamicSharedMemorySize, smem1);
    cudaFuncSetAttribute(k4_final,    cudaFuncAttributeMaxDynamicSharedMemorySize, smem4);

    k1_ln_conv1<<<dim3(HWP/TP1, BB), 256, smem1>>>(inp, probs, w1, la1, lb1, ln1w, ln1b, b1);
    k2_dw_gate_pool<<<dim3(HH/8, CC, BB), 256>>>(probs, w2, la2, lb2, b2);
    k4_final<<<dim3(HWP/TP4, BB), 256, smem4>>>(inp, probs,
        wsca, bsca, la_s, lb_s, w3, b3, la3, lb3, w4, b4, la4, lb4,
        w5, b5, la5, lb5, ln2w, ln2b, beta, gamma, out);
}

// round 10
// speedup vs baseline: 1.3486x; 1.3486x over previous
#include <cuda_runtime.h>
#include <cuda_bf16.h>
#include <mma.h>
using namespace nvcuda;

#define BB 4
#define CC 64
#define DWC 128
#define HH 256
#define WW 256
#define HWP (HH*WW)
#define HWP2 (HWP/2)
#define EPSF 1e-6f

typedef unsigned long long u64;
typedef unsigned int u32;

static __device__ __forceinline__ u32 pack_bf16(float lo, float hi) {
    u32 r;
    asm("cvt.rn.bf16x2.f32 %0, %1, %2;" : "=r"(r) : "f"(hi), "f"(lo));
    return r;
}
static __device__ __forceinline__ float2 bf16pair_to_f2(u32 v) {
    __nv_bfloat162 b = *reinterpret_cast<__nv_bfloat162*>(&v);
    return __bfloat1622float2(b);
}
static __device__ __forceinline__ float topk_gate(const float* probs, int b, int& be) {
    float best = probs[b*3]; be = 0;
    #pragma unroll
    for (int e = 1; e < 3; e++) {
        float p = probs[b*3+e];
        if (p > best) { best = p; be = e; }
    }
    return best * 2.0f;  // gate * SCALING
}

// ---------------- device scratch ----------------
__device__ u32 g_w1b[BB][DWC][32];      // conv1 eff weights, bf16 pairs [oc][k/2]
__device__ u32 g_w3b[BB][CC][32];
__device__ u32 g_w4b[BB][DWC][32];
__device__ u32 g_w5b[BB][CC][32];
__device__ float g_wscaf[BB][CC][CC];   // sca eff weights fp32
__device__ u32 g_u[BB][DWC][HWP2];      // conv1 out, bf16 pairs (64 MB)
__device__ u32 g_t[BB][CC][HWP2];       // gated out, bf16 pairs (32 MB)
__device__ float g_poolpart[BB][CC][32];

// ---------------- K0: gate + effective weights (bf16) ----------------
__global__ void k0_weights(const float* __restrict__ probs,
    const float* __restrict__ w1, const float* __restrict__ la1, const float* __restrict__ lb1,
    const float* __restrict__ w3, const float* __restrict__ la3, const float* __restrict__ lb3,
    const float* __restrict__ w4, const float* __restrict__ la4, const float* __restrict__ lb4,
    const float* __restrict__ w5, const float* __restrict__ la5, const float* __restrict__ lb5,
    const float* __restrict__ wsca, const float* __restrict__ lasca, const float* __restrict__ lbsca)
{
    int b = blockIdx.x, t = threadIdx.x;
    int be; float g = topk_gate(probs, b, be);

    // conv1/conv4: 128x64
    for (int idx = t; idx < DWC*32; idx += 256) {
        int o = idx >> 5, p = idx & 31;
        int i0 = 2*p, i1 = 2*p+1;
        float e10 = 0.f, e11 = 0.f, e40 = 0.f, e41 = 0.f;
        #pragma unroll
        for (int r = 0; r < 4; r++) {
            float lbv1 = lb1[(be*DWC+o)*4+r], lbv4 = lb4[(be*DWC+o)*4+r];
            e10 += lbv1 * la1[(be*4+r)*CC+i0];
            e11 += lbv1 * la1[(be*4+r)*CC+i1];
            e40 += lbv4 * la4[(be*4+r)*CC+i0];
            e41 += lbv4 * la4[(be*4+r)*CC+i1];
        }
        g_w1b[b][o][p] = pack_bf16(w1[o*CC+i0] + g*e10, w1[o*CC+i1] + g*e11);
        g_w4b[b][o][p] = pack_bf16(w4[o*CC+i0] + g*e40, w4[o*CC+i1] + g*e41);
    }
    // conv3/conv5: 64x64
    for (int idx = t; idx < CC*32; idx += 256) {
        int o = idx >> 5, p = idx & 31;
        int i0 = 2*p, i1 = 2*p+1;
        float e30 = 0.f, e31 = 0.f, e50 = 0.f, e51 = 0.f;
        #pragma unroll
        for (int r = 0; r < 4; r++) {
            float lbv3 = lb3[(be*CC+o)*4+r], lbv5 = lb5[(be*CC+o)*4+r];
            e30 += lbv3 * la3[(be*4+r)*CC+i0];
            e31 += lbv3 * la3[(be*4+r)*CC+i1];
            e50 += lbv5 * la5[(be*4+r)*CC+i0];
            e51 += lbv5 * la5[(be*4+r)*CC+i1];
        }
        g_w3b[b][o][p] = pack_bf16(w3[o*CC+i0] + g*e30, w3[o*CC+i1] + g*e31);
        g_w5b[b][o][p] = pack_bf16(w5[o*CC+i0] + g*e50, w5[o*CC+i1] + g*e51);
    }
    // sca: fp32
    for (int idx = t; idx < CC*CC; idx += 256) {
        int o = idx >> 6, i = idx & 63;
        float s = 0.f;
        #pragma unroll
        for (int r = 0; r < 4; r++)
            s += lbsca[(be*CC+o)*4+r] * lasca[(be*4+r)*CC+i];
        g_wscaf[b][o][i] = wsca[idx] + g*s;
    }
}

// ---------------- K1: LN1 + conv1 (64->128) via wmma, 128-pix tiles ----------------
#define XB_LD 136
#define W_LD 72

__global__ __launch_bounds__(256) void k1_ln_conv1(
    const float* __restrict__ inp, const float* __restrict__ ln1w,
    const float* __restrict__ ln1b, const float* __restrict__ b1)
{
    extern __shared__ char smraw[];
    __nv_bfloat16* w1s = (__nv_bfloat16*)smraw;            // [128][72]  18432B
    __nv_bfloat16* xb  = w1s + DWC*W_LD;                   // [64][136]  17408B
    float* stg  = (float*)(xb + CC*XB_LD);                 // [8][256]   8192B
    float* psum = stg + 8*256;                             // 256
    float* psq  = psum + 256;                              // 256
    float* mu   = psq + 256;                               // 128
    float* rstd = mu + 128;                                // 128
    float* bias1 = rstd + 128;                             // 128
    float* lnw  = bias1 + 128;                             // 64
    float* lnb  = lnw + 64;                                // 64

    int b = blockIdx.y;
    int pixbase = blockIdx.x * 128;
    int t = threadIdx.x;
    int pix = t & 127, crow = t >> 7;

    const float* X = inp + (size_t)b*CC*HWP + pixbase;
    float vreg[32];
    float s = 0.f, sq = 0.f;
    #pragma unroll
    for (int i = 0; i < 32; i++) {
        int c = crow + 2*i;
        float v = X[(size_t)c*HWP + pix];
        vreg[i] = v; s += v; sq += v*v;
    }
    psum[crow*128+pix] = s; psq[crow*128+pix] = sq;

    // stage weights + constants
    u32* w1su = (u32*)w1s;   // row stride 36 u32
    for (int idx = t; idx < DWC*32; idx += 256) {
        int o = idx >> 5, p = idx & 31;
        w1su[o*36 + p] = g_w1b[b][o][p];
    }
    if (t < 128) bias1[t] = b1[t];
    if (t < 64) { lnw[t] = ln1w[t]; lnb[t] = ln1b[t]; }
    __syncthreads();

    if (t < 128) {
        float m = (psum[t]+psum[128+t]) * (1.f/CC);
        float var = (psq[t]+psq[128+t]) * (1.f/CC) - m*m;
        mu[t] = m; rstd[t] = rsqrtf(var + EPSF);
    }
    __syncthreads();

    float mpix = mu[pix], rpix = rstd[pix];
    #pragma unroll
    for (int i = 0; i < 32; i++) {
        int c = crow + 2*i;
        xb[c*XB_LD + pix] = __float2bfloat16((vreg[i]-mpix)*rpix*lnw[c] + lnb[c]);
    }
    __syncthreads();

    // MMA: warp w handles oc rows [16w,16w+16), all 8 pixel tiles
    int w = t >> 5, lane = t & 31;
    wmma::fragment<wmma::matrix_a, 16, 16, 16, __nv_bfloat16, wmma::row_major> af[4];
    #pragma unroll
    for (int kt = 0; kt < 4; kt++)
        wmma::load_matrix_sync(af[kt], w1s + (w*16)*W_LD + kt*16, W_LD);
    float* stgw = stg + w*256;

    for (int pc = 0; pc < 8; pc++) {
        wmma::fragment<wmma::accumulator, 16, 16, 16, float> acc;
        wmma::fill_fragment(acc, 0.f);
        #pragma unroll
        for (int kt = 0; kt < 4; kt++) {
            wmma::fragment<wmma::matrix_b, 16, 16, 16, __nv_bfloat16, wmma::row_major> bf;
            wmma::load_matrix_sync(bf, xb + (kt*16)*XB_LD + pc*16, XB_LD);
            wmma::mma_sync(acc, af[kt], bf, acc);
        }
        wmma::store_matrix_sync(stgw, acc, 16, wmma::mem_row_major);
        __syncwarp();
        int colbase = (pixbase >> 1) + pc*8;
        #pragma unroll
        for (int j = 0; j < 4; j++) {
            int lin = lane*4 + j;
            int row = lin >> 3, pr = lin & 7;
            float bb = bias1[w*16 + row];
            g_u[b][w*16+row][colbase + pr] =
                pack_bf16(stgw[row*16 + 2*pr] + bb, stgw[row*16 + 2*pr + 1] + bb);
        }
        __syncwarp();
    }
}

// ---------------- K2: depthwise 3x3 + SimpleGate + pool partials ----------------
__global__ __launch_bounds__(256) void k2_dw_gate_pool(
    const float* __restrict__ probs,
    const float* __restrict__ w2, const float* __restrict__ la2, const float* __restrict__ lb2,
    const float* __restrict__ b2)
{
    __shared__ float u0[10*258];
    __shared__ float u1[10*258];
    __shared__ float wsm[18];
    __shared__ float redbuf[8];
    int b = blockIdx.z, j = blockIdx.y;
    int r0 = blockIdx.x * 8;
    int t = threadIdx.x;
    int be; float g = topk_gate(probs, b, be);

    if (t < 18) {
        int ch = (t < 9) ? j : (j + CC);
        int kk = t % 9, kh = kk / 3, kw = kk % 3;
        float s = 0.f;
        #pragma unroll
        for (int r = 0; r < 12; r++)
            s += lb2[(be*384 + ch*3 + kh)*12 + r] * la2[(be*12+r)*3 + kw];
        wsm[t] = w2[ch*9 + kk] + g*s;
    }

    const u32* U0 = g_u[b][j];
    const u32* U1 = g_u[b][j+CC];
    for (int idx = t; idx < 10*128; idx += 256) {
        int rr = idx >> 7, cp = idx & 127;
        int row = r0 - 1 + rr;
        float2 v0 = make_float2(0.f, 0.f), v1 = v0;
        if (row >= 0 && row < HH) {
            v0 = bf16pair_to_f2(U0[row*128 + cp]);
            v1 = bf16pair_to_f2(U1[row*128 + cp]);
        }
        u0[rr*258 + 1 + 2*cp] = v0.x; u0[rr*258 + 2 + 2*cp] = v0.y;
        u1[rr*258 + 1 + 2*cp] = v1.x; u1[rr*258 + 2 + 2*cp] = v1.y;
    }
    if (t < 10) { u0[t*258] = 0.f; u1[t*258] = 0.f; }
    else if (t < 20) { int rr = t-10; u0[rr*258+257] = 0.f; u1[rr*258+257] = 0.f; }
    __syncthreads();

    float wa[9], wb[9];
    #pragma unroll
    for (int i = 0; i < 9; i++) { wa[i] = wsm[i]; wb[i] = wsm[9+i]; }
    float biasA = b2[j], biasB = b2[j+CC];

    int cp = t & 127, rg = t >> 7;
    int c0 = 2*cp;
    float lsum = 0.f;
    #pragma unroll
    for (int ii = 0; ii < 4; ii++) {
        int orow = rg*4 + ii;
        float a0 = biasA, a1 = biasA, c0v = biasB, c1v = biasB;
        #pragma unroll
        for (int kh = 0; kh < 3; kh++) {
            const float* r0p = u0 + (orow+kh)*258 + c0;
            const float* r1p = u1 + (orow+kh)*258 + c0;
            float2 x01 = *(const float2*)r0p;
            float2 x23 = *(const float2*)(r0p+2);
            float2 y01 = *(const float2*)r1p;
            float2 y23 = *(const float2*)(r1p+2);
            a0 = fmaf(wa[kh*3+0], x01.x, a0); a0 = fmaf(wa[kh*3+1], x01.y, a0); a0 = fmaf(wa[kh*3+2], x23.x, a0);
            a1 = fmaf(wa[kh*3+0], x01.y, a1); a1 = fmaf(wa[kh*3+1], x23.x, a1); a1 = fmaf(wa[kh*3+2], x23.y, a1);
            c0v = fmaf(wb[kh*3+0], y01.x, c0v); c0v = fmaf(wb[kh*3+1], y01.y, c0v); c0v = fmaf(wb[kh*3+2], y23.x, c0v);
            c1v = fmaf(wb[kh*3+0], y01.y, c1v); c1v = fmaf(wb[kh*3+1], y23.x, c1v); c1v = fmaf(wb[kh*3+2], y23.y, c1v);
        }
        float p0v = a0 * c0v, p1v = a1 * c1v;
        g_t[b][j][(r0+orow)*128 + cp] = pack_bf16(p0v, p1v);
        lsum += p0v + p1v;
    }
    #pragma unroll
    for (int off = 16; off > 0; off >>= 1) lsum += __shfl_down_sync(0xffffffffu, lsum, off);
    if ((t & 31) == 0) redbuf[t >> 5] = lsum;
    __syncthreads();
    if (t == 0) {
        float tot = 0.f;
        #pragma unroll
        for (int i = 0; i < 8; i++) tot += redbuf[i];
        g_poolpart[b][j][blockIdx.x] = tot;
    }
}

// ---------------- K4: fused tail via wmma, 64-pixel tiles ----------------
#define DLD 68
#define YLD 68

__global__ __launch_bounds__(256) void k4_final(
    const float* __restrict__ inp, const float* __restrict__ probs,
    const float* __restrict__ bsca,
    const float* __restrict__ b3, const float* __restrict__ b4, const float* __restrict__ b5,
    const float* __restrict__ ln2w, const float* __restrict__ ln2b,
    const float* __restrict__ beta, const float* __restrict__ gamma,
    float* __restrict__ out)
{
    extern __shared__ char smraw[];
    __nv_bfloat16* w3s = (__nv_bfloat16*)smraw;    // [64][72]   9216B
    __nv_bfloat16* w4s = w3s + CC*W_LD;            // [128][72]  18432B
    __nv_bfloat16* w5s = w4s + DWC*W_LD;           // [64][72]   9216B
    __nv_bfloat16* xb  = w5s + CC*W_LD;            // [64][72]   9216B
    float* Dst  = (float*)(xb + CC*W_LD);          // [128][68]  34816B
    float* y    = Dst + DWC*DLD;                   // [64][68]   17408B
    float* pl   = y + CC*YLD;                      // 64
    float* scas = pl + 64;                         // 64
    float* mu   = scas + 64;                       // 64
    float* rstd = mu + 64;                         // 64
    float* redS = rstd + 64;                       // 256
    float* redQ = redS + 256;                      // 256
    float* sb3  = redQ + 256;                      // 64
    float* sb4  = sb3 + 64;                        // 128
    float* sb5  = sb4 + 128;                       // 64
    float* sbeta = sb5 + 64;                       // 64
    float* sgamma = sbeta + 64;                    // 64
    float* slnw = sgamma + 64;                     // 64
    float* slnb = slnw + 64;                       // 64

    int b = blockIdx.y;
    int pixbase = blockIdx.x * 64;
    int t = threadIdx.x;
    int w = t >> 5, lane = t & 31;
    (void)lane;

    // stage weights (bf16 pairs) + constants
    u32* w3u = (u32*)w3s; u32* w4u = (u32*)w4s; u32* w5u = (u32*)w5s;
    for (int idx = t; idx < CC*32; idx += 256) {
        int o = idx >> 5, p = idx & 31;
        w3u[o*36+p] = g_w3b[b][o][p];
        w5u[o*36+p] = g_w5b[b][o][p];
    }
    for (int idx = t; idx < DWC*32; idx += 256) {
        int o = idx >> 5, p = idx & 31;
        w4u[o*36+p] = g_w4b[b][o][p];
    }
    if (t < 64) {
        float s = 0.f;
        #pragma unroll
        for (int p = 0; p < 32; p++) s += g_poolpart[b][t][p];
        pl[t] = s;
        sb3[t] = b3[t]; sb5[t] = b5[t];
        sbeta[t] = beta[t]; sgamma[t] = gamma[t];
        slnw[t] = ln2w[t]; slnb[t] = ln2b[t];
    }
    if (t < 128) sb4[t] = b4[t];
    __syncthreads();

    if (t < 64) {
        float acc = 0.f;
        #pragma unroll 8
        for (int i = 0; i < CC; i++) acc += g_wscaf[b][t][i] * pl[i];
        scas[t] = bsca[t] + acc * (1.f/HWP);
    }
    __syncthreads();

    // xb = bf16(t * sca)
    int prb = pixbase >> 1;
    u32* xbu = (u32*)xb;
    for (int idx = t; idx < CC*32; idx += 256) {
        int c = idx >> 5, pr = idx & 31;
        float2 f = bf16pair_to_f2(g_t[b][c][prb + pr]);
        float sc = scas[c];
        xbu[c*36 + pr] = pack_bf16(f.x*sc, f.y*sc);
    }
    __syncthreads();

    // ---- conv3 (64->64): warp w -> ocRow r=w&3, pixCols {(w>>2)*2, +1}
    {
        int r = w & 3;
        wmma::fragment<wmma::matrix_a, 16, 16, 16, __nv_bfloat16, wmma::row_major> af[4];
        #pragma unroll
        for (int kt = 0; kt < 4; kt++)
            wmma::load_matrix_sync(af[kt], w3s + (r*16)*W_LD + kt*16, W_LD);
        #pragma unroll
        for (int pi = 0; pi < 2; pi++) {
            int pc = (w >> 2)*2 + pi;
            wmma::fragment<wmma::accumulator, 16, 16, 16, float> acc;
            wmma::fill_fragment(acc, 0.f);
            #pragma unroll
            for (int kt = 0; kt < 4; kt++) {
                wmma::fragment<wmma::matrix_b, 16, 16, 16, __nv_bfloat16, wmma::row_major> bf;
                wmma::load_matrix_sync(bf, xb + (kt*16)*W_LD + pc*16, W_LD);
                wmma::mma_sync(acc, af[kt], bf, acc);
            }
            wmma::store_matrix_sync(Dst + (r*16)*DLD + pc*16, acc, DLD, wmma::mem_row_major);
        }
    }
    __syncthreads();

    // y = inp + (conv3 + b3) * beta
    for (int idx = t; idx < CC*64; idx += 256) {
        int c = idx >> 6, px = idx & 63;
        float d = Dst[c*DLD + px];
        float yv = inp[((size_t)(b*CC+c))*HWP + pixbase + px] + (d + sb3[c]) * sbeta[c];
        y[c*YLD + px] = yv;
    }
    __syncthreads();

    // LN2 stats over channels per pixel
    {
        int q = t >> 6, pp = t & 63;
        float s = 0.f, sq = 0.f;
        #pragma unroll
        for (int i = 0; i < 16; i++) {
            float v = y[(q*16+i)*YLD + pp];
            s += v; sq += v*v;
        }
        redS[q*64+pp] = s; redQ[q*64+pp] = sq;
    }
    __syncthreads();
    if (t < 64) {
        float s  = redS[t] + redS[64+t] + redS[128+t] + redS[192+t];
        float sq = redQ[t] + redQ[64+t] + redQ[128+t] + redQ[192+t];
        float m = s * (1.f/CC);
        float var = sq * (1.f/CC) - m*m;
        mu[t] = m; rstd[t] = rsqrtf(var + EPSF);
    }
    __syncthreads();

    // xb = bf16(ln2(y))
    for (int idx = t; idx < CC*32; idx += 256) {
        int c = idx >> 5, pr = idx & 31;
        int px = 2*pr;
        float n0 = (y[c*YLD+px]   - mu[px])   * rstd[px]   * slnw[c] + slnb[c];
        float n1 = (y[c*YLD+px+1] - mu[px+1]) * rstd[px+1] * slnw[c] + slnb[c];
        xbu[c*36 + pr] = pack_bf16(n0, n1);
    }
    __syncthreads();

    // ---- conv4 (64->128): warp w -> ocRow w, pixCols 0..3
    {
        wmma::fragment<wmma::matrix_a, 16, 16, 16, __nv_bfloat16, wmma::row_major> af[4];
        #pragma unroll
        for (int kt = 0; kt < 4; kt++)
            wmma::load_matrix_sync(af[kt], w4s + (w*16)*W_LD + kt*16, W_LD);
        #pragma unroll
        for (int pc = 0; pc < 4; pc++) {
            wmma::fragment<wmma::accumulator, 16, 16, 16, float> acc;
            wmma::fill_fragment(acc, 0.f);
            #pragma unroll
            for (int kt = 0; kt < 4; kt++) {
                wmma::fragment<wmma::matrix_b, 16, 16, 16, __nv_bfloat16, wmma::row_major> bf;
                wmma::load_matrix_sync(bf, xb + (kt*16)*W_LD + pc*16, W_LD);
                wmma::mma_sync(acc, af[kt], bf, acc);
            }
            wmma::store_matrix_sync(Dst + (w*16)*DLD + pc*16, acc, DLD, wmma::mem_row_major);
        }
    }
    __syncthreads();

    // SimpleGate -> xb
    for (int idx = t; idx < CC*32; idx += 256) {
        int c = idx >> 5, pr = idx & 31;
        int px = 2*pr;
        float x10 = Dst[c*DLD+px]   + sb4[c];
        float x11 = Dst[c*DLD+px+1] + sb4[c];
        float x20 = Dst[(c+CC)*DLD+px]   + sb4[c+CC];
        float x21 = Dst[(c+CC)*DLD+px+1] + sb4[c+CC];
        xbu[c*36 + pr] = pack_bf16(x10*x20, x11*x21);
    }
    __syncthreads();

    // ---- conv5 (64->64): like conv3
    {
        int r = w & 3;
        wmma::fragment<wmma::matrix_a, 16, 16, 16, __nv_bfloat16, wmma::row_major> af[4];
        #pragma unroll
        for (int kt = 0; kt < 4; kt++)
            wmma::load_matrix_sync(af[kt], w5s + (r*16)*W_LD + kt*16, W_LD);
        #pragma unroll
        for (int pi = 0; pi < 2; pi++) {
            int pc = (w >> 2)*2 + pi;
            wmma::fragment<wmma::accumulator, 16, 16, 16, float> acc;
            wmma::fill_fragment(acc, 0.f);
            #pragma unroll
            for (int kt = 0; kt < 4; kt++) {
                wmma::fragment<wmma::matrix_b, 16, 16, 16, __nv_bfloat16, wmma::row_major> bf;
                wmma::load_matrix_sync(bf, xb + (kt*16)*W_LD + pc*16, W_LD);
                wmma::mma_sync(acc, af[kt], bf, acc);
            }
            wmma::store_matrix_sync(Dst + (r*16)*DLD + pc*16, acc, DLD, wmma::mem_row_major);
        }
    }
    __syncthreads();

    // out = y + (conv5 + b5) * gamma
    for (int idx = t; idx < CC*32; idx += 256) {
        int c = idx >> 5, pr = idx & 31;
        int px = 2*pr;
        float g0 = y[c*YLD+px]   + (Dst[c*DLD+px]   + sb5[c]) * sgamma[c];
        float g1 = y[c*YLD+px+1] + (Dst[c*DLD+px+1] + sb5[c]) * sgamma[c];
        *(float2*)(out + ((size_t)(b*CC+c))*HWP + pixbase + px) = make_float2(g0, g1);
    }
}

// ---------------- launch ----------------
extern "C" void kernel_launch(void* const* d_in, const int* in_sizes, int n_in,
                              void* d_out, int out_size)
{
    const float* inp   = (const float*)d_in[0];
    const float* probs = (const float*)d_in[1];
    const float* ln1w  = (const float*)d_in[2];
    const float* ln1b  = (const float*)d_in[3];
    const float* ln2w  = (const float*)d_in[4];
    const float* ln2b  = (const float*)d_in[5];
    const float* w1    = (const float*)d_in[6];
    const float* b1    = (const float*)d_in[7];
    const float* la1   = (const float*)d_in[8];
    const float* lb1   = (const float*)d_in[9];
    const float* w2    = (const float*)d_in[10];
    const float* b2    = (const float*)d_in[11];
    const float* la2   = (const float*)d_in[12];
    const float* lb2   = (const float*)d_in[13];
    const float* wsca  = (const float*)d_in[14];
    const float* bsca  = (const float*)d_in[15];
    const float* la_s  = (const float*)d_in[16];
    const float* lb_s  = (const float*)d_in[17];
    const float* w3    = (const float*)d_in[18];
    const float* b3    = (const float*)d_in[19];
    const float* la3   = (const float*)d_in[20];
    const float* lb3   = (const float*)d_in[21];
    const float* w4    = (const float*)d_in[22];
    const float* b4    = (const float*)d_in[23];
    const float* la4   = (const float*)d_in[24];
    const float* lb4   = (const float*)d_in[25];
    const float* w5    = (const float*)d_in[26];
    const float* b5    = (const float*)d_in[27];
    const float* la5   = (const float*)d_in[28];
    const float* lb5   = (const float*)d_in[29];
    const float* beta  = (const float*)d_in[30];
    const float* gamma = (const float*)d_in[31];
    float* out = (float*)d_out;

    const int smem1 = DWC*W_LD*2 + CC*XB_LD*2 + 8*256*4
                    + (256+256+128+128+128+64+64)*4;                   // 48128
    const int smem4 = (CC*W_LD + DWC*W_LD + CC*W_LD + CC*W_LD)*2
                    + DWC*DLD*4 + CC*YLD*4
                    + (64+64+64+64+256+256+64+128+64+64+64+64+64)*4;   // 103424
    cudaFuncSetAttribute(k1_ln_conv1, cudaFuncAttributeMaxDynamicSharedMemorySize, smem1);
    cudaFuncSetAttribute(k4_final,    cudaFuncAttributeMaxDynamicSharedMemorySize, smem4);

    k0_weights<<<BB, 256>>>(probs, w1, la1, lb1, w3, la3, lb3,
                            w4, la4, lb4, w5, la5, lb5, wsca, la_s, lb_s);
    k1_ln_conv1<<<dim3(HWP/128, BB), 256, smem1>>>(inp, ln1w, ln1b, b1);
    k2_dw_gate_pool<<<dim3(HH/8, CC, BB), 256>>>(probs, w2, la2, lb2, b2);
    k4_final<<<dim3(HWP/64, BB), 256, smem4>>>(inp, probs, bsca, b3, b4, b5,
                                               ln2w, ln2b, beta, gamma, out);
}

// round 12
// speedup vs baseline: 1.8321x; 1.3585x over previous
#include <cuda_runtime.h>
#include <cuda_bf16.h>
#include <mma.h>
using namespace nvcuda;

#define BB 4
#define CC 64
#define DWC 128
#define HH 256
#define WW 256
#define HWP (HH*WW)
#define HWP2 (HWP/2)
#define EPSF 1e-6f

typedef unsigned long long u64;
typedef unsigned int u32;

static __device__ __forceinline__ u32 pack_bf16(float lo, float hi) {
    u32 r;
    asm("cvt.rn.bf16x2.f32 %0, %1, %2;" : "=r"(r) : "f"(hi), "f"(lo));
    return r;
}
static __device__ __forceinline__ float2 bf16pair_to_f2(u32 v) {
    __nv_bfloat162 b = *reinterpret_cast<__nv_bfloat162*>(&v);
    return __bfloat1622float2(b);
}
static __device__ __forceinline__ float topk_gate(const float* probs, int b, int& be) {
    float best = probs[b*3]; be = 0;
    #pragma unroll
    for (int e = 1; e < 3; e++) {
        float p = probs[b*3+e];
        if (p > best) { best = p; be = e; }
    }
    return best * 2.0f;  // gate * SCALING
}

// ---------------- device scratch ----------------
__device__ u32 g_w1b[BB][DWC][32];      // conv1 eff weights, bf16 pairs [oc][k/2]
__device__ u32 g_w3b[BB][CC][32];
__device__ u32 g_w4b[BB][DWC][32];
__device__ u32 g_w5b[BB][CC][32];
__device__ float g_wscaf[BB][CC][CC];   // sca eff weights fp32
__device__ u32 g_u[BB][DWC][HWP2];      // conv1 out, bf16 pairs (64 MB)
__device__ u32 g_t[BB][CC][HWP2];       // gated out, bf16 pairs (32 MB)
__device__ float g_poolpart[BB][CC][32];

// ---------------- K0: gate + effective weights (bf16) ----------------
__global__ void k0_weights(const float* __restrict__ probs,
    const float* __restrict__ w1, const float* __restrict__ la1, const float* __restrict__ lb1,
    const float* __restrict__ w3, const float* __restrict__ la3, const float* __restrict__ lb3,
    const float* __restrict__ w4, const float* __restrict__ la4, const float* __restrict__ lb4,
    const float* __restrict__ w5, const float* __restrict__ la5, const float* __restrict__ lb5,
    const float* __restrict__ wsca, const float* __restrict__ lasca, const float* __restrict__ lbsca)
{
    int b = blockIdx.x, t = threadIdx.x;
    int be; float g = topk_gate(probs, b, be);

    for (int idx = t; idx < DWC*32; idx += 256) {
        int o = idx >> 5, p = idx & 31;
        int i0 = 2*p, i1 = 2*p+1;
        float e10 = 0.f, e11 = 0.f, e40 = 0.f, e41 = 0.f;
        #pragma unroll
        for (int r = 0; r < 4; r++) {
            float lbv1 = lb1[(be*DWC+o)*4+r], lbv4 = lb4[(be*DWC+o)*4+r];
            e10 += lbv1 * la1[(be*4+r)*CC+i0];
            e11 += lbv1 * la1[(be*4+r)*CC+i1];
            e40 += lbv4 * la4[(be*4+r)*CC+i0];
            e41 += lbv4 * la4[(be*4+r)*CC+i1];
        }
        g_w1b[b][o][p] = pack_bf16(w1[o*CC+i0] + g*e10, w1[o*CC+i1] + g*e11);
        g_w4b[b][o][p] = pack_bf16(w4[o*CC+i0] + g*e40, w4[o*CC+i1] + g*e41);
    }
    for (int idx = t; idx < CC*32; idx += 256) {
        int o = idx >> 5, p = idx & 31;
        int i0 = 2*p, i1 = 2*p+1;
        float e30 = 0.f, e31 = 0.f, e50 = 0.f, e51 = 0.f;
        #pragma unroll
        for (int r = 0; r < 4; r++) {
            float lbv3 = lb3[(be*CC+o)*4+r], lbv5 = lb5[(be*CC+o)*4+r];
            e30 += lbv3 * la3[(be*4+r)*CC+i0];
            e31 += lbv3 * la3[(be*4+r)*CC+i1];
            e50 += lbv5 * la5[(be*4+r)*CC+i0];
            e51 += lbv5 * la5[(be*4+r)*CC+i1];
        }
        g_w3b[b][o][p] = pack_bf16(w3[o*CC+i0] + g*e30, w3[o*CC+i1] + g*e31);
        g_w5b[b][o][p] = pack_bf16(w5[o*CC+i0] + g*e50, w5[o*CC+i1] + g*e51);
    }
    for (int idx = t; idx < CC*CC; idx += 256) {
        int o = idx >> 6, i = idx & 63;
        float s = 0.f;
        #pragma unroll
        for (int r = 0; r < 4; r++)
            s += lbsca[(be*CC+o)*4+r] * lasca[(be*4+r)*CC+i];
        g_wscaf[b][o][i] = wsca[idx] + g*s;
    }
}

// ---------------- K1: LN1 + conv1 (64->128) via wmma, 128-pix tiles ----------------
#define XB_LD 136
#define W_LD 72

__global__ __launch_bounds__(256) void k1_ln_conv1(
    const float* __restrict__ inp, const float* __restrict__ ln1w,
    const float* __restrict__ ln1b, const float* __restrict__ b1)
{
    extern __shared__ char smraw[];
    __nv_bfloat16* w1s = (__nv_bfloat16*)smraw;            // [128][72]
    __nv_bfloat16* xb  = w1s + DWC*W_LD;                   // [64][136]
    float* stg  = (float*)(xb + CC*XB_LD);                 // [8][256]
    float* psum = stg + 8*256;
    float* psq  = psum + 256;
    float* mu   = psq + 256;
    float* rstd = mu + 128;
    float* bias1 = rstd + 128;
    float* lnw  = bias1 + 128;
    float* lnb  = lnw + 64;

    int b = blockIdx.y;
    int pixbase = blockIdx.x * 128;
    int t = threadIdx.x;
    int pix = t & 127, crow = t >> 7;

    const float* X = inp + (size_t)b*CC*HWP + pixbase;
    float vreg[32];
    float s = 0.f, sq = 0.f;
    #pragma unroll
    for (int i = 0; i < 32; i++) {
        int c = crow + 2*i;
        float v = X[(size_t)c*HWP + pix];
        vreg[i] = v; s += v; sq += v*v;
    }
    psum[crow*128+pix] = s; psq[crow*128+pix] = sq;

    u32* w1su = (u32*)w1s;
    for (int idx = t; idx < DWC*32; idx += 256) {
        int o = idx >> 5, p = idx & 31;
        w1su[o*36 + p] = g_w1b[b][o][p];
    }
    if (t < 128) bias1[t] = b1[t];
    if (t < 64) { lnw[t] = ln1w[t]; lnb[t] = ln1b[t]; }
    __syncthreads();

    if (t < 128) {
        float m = (psum[t]+psum[128+t]) * (1.f/CC);
        float var = (psq[t]+psq[128+t]) * (1.f/CC) - m*m;
        mu[t] = m; rstd[t] = rsqrtf(var + EPSF);
    }
    __syncthreads();

    float mpix = mu[pix], rpix = rstd[pix];
    #pragma unroll
    for (int i = 0; i < 32; i++) {
        int c = crow + 2*i;
        xb[c*XB_LD + pix] = __float2bfloat16((vreg[i]-mpix)*rpix*lnw[c] + lnb[c]);
    }
    __syncthreads();

    int w = t >> 5, lane = t & 31;
    wmma::fragment<wmma::matrix_a, 16, 16, 16, __nv_bfloat16, wmma::row_major> af[4];
    #pragma unroll
    for (int kt = 0; kt < 4; kt++)
        wmma::load_matrix_sync(af[kt], w1s + (w*16)*W_LD + kt*16, W_LD);
    float* stgw = stg + w*256;

    for (int pc = 0; pc < 8; pc++) {
        wmma::fragment<wmma::accumulator, 16, 16, 16, float> acc;
        wmma::fill_fragment(acc, 0.f);
        #pragma unroll
        for (int kt = 0; kt < 4; kt++) {
            wmma::fragment<wmma::matrix_b, 16, 16, 16, __nv_bfloat16, wmma::row_major> bf;
            wmma::load_matrix_sync(bf, xb + (kt*16)*XB_LD + pc*16, XB_LD);
            wmma::mma_sync(acc, af[kt], bf, acc);
        }
        wmma::store_matrix_sync(stgw, acc, 16, wmma::mem_row_major);
        __syncwarp();
        int colbase = (pixbase >> 1) + pc*8;
        #pragma unroll
        for (int j = 0; j < 4; j++) {
            int lin = lane*4 + j;
            int row = lin >> 3, pr = lin & 7;
            float bb = bias1[w*16 + row];
            g_u[b][w*16+row][colbase + pr] =
                pack_bf16(stgw[row*16 + 2*pr] + bb, stgw[row*16 + 2*pr + 1] + bb);
        }
        __syncwarp();
    }
}

// ---------------- K2: depthwise 3x3 + SimpleGate + pool partials ----------------
__global__ __launch_bounds__(256) void k2_dw_gate_pool(
    const float* __restrict__ probs,
    const float* __restrict__ w2, const float* __restrict__ la2, const float* __restrict__ lb2,
    const float* __restrict__ b2)
{
    __shared__ float u0[10*258];
    __shared__ float u1[10*258];
    __shared__ float wsm[18];
    __shared__ float redbuf[8];
    int b = blockIdx.z, j = blockIdx.y;
    int r0 = blockIdx.x * 8;
    int t = threadIdx.x;
    int be; float g = topk_gate(probs, b, be);

    if (t < 18) {
        int ch = (t < 9) ? j : (j + CC);
        int kk = t % 9, kh = kk / 3, kw = kk % 3;
        float s = 0.f;
        #pragma unroll
        for (int r = 0; r < 12; r++)
            s += lb2[(be*384 + ch*3 + kh)*12 + r] * la2[(be*12+r)*3 + kw];
        wsm[t] = w2[ch*9 + kk] + g*s;
    }

    const u32* U0 = g_u[b][j];
    const u32* U1 = g_u[b][j+CC];
    for (int idx = t; idx < 10*128; idx += 256) {
        int rr = idx >> 7, cp = idx & 127;
        int row = r0 - 1 + rr;
        float2 v0 = make_float2(0.f, 0.f), v1 = v0;
        if (row >= 0 && row < HH) {
            v0 = bf16pair_to_f2(U0[row*128 + cp]);
            v1 = bf16pair_to_f2(U1[row*128 + cp]);
        }
        u0[rr*258 + 1 + 2*cp] = v0.x; u0[rr*258 + 2 + 2*cp] = v0.y;
        u1[rr*258 + 1 + 2*cp] = v1.x; u1[rr*258 + 2 + 2*cp] = v1.y;
    }
    if (t < 10) { u0[t*258] = 0.f; u1[t*258] = 0.f; }
    else if (t < 20) { int rr = t-10; u0[rr*258+257] = 0.f; u1[rr*258+257] = 0.f; }
    __syncthreads();

    float wa[9], wb[9];
    #pragma unroll
    for (int i = 0; i < 9; i++) { wa[i] = wsm[i]; wb[i] = wsm[9+i]; }
    float biasA = b2[j], biasB = b2[j+CC];

    int cp = t & 127, rg = t >> 7;
    int c0 = 2*cp;
    float lsum = 0.f;
    #pragma unroll
    for (int ii = 0; ii < 4; ii++) {
        int orow = rg*4 + ii;
        float a0 = biasA, a1 = biasA, c0v = biasB, c1v = biasB;
        #pragma unroll
        for (int kh = 0; kh < 3; kh++) {
            const float* r0p = u0 + (orow+kh)*258 + c0;
            const float* r1p = u1 + (orow+kh)*258 + c0;
            float2 x01 = *(const float2*)r0p;
            float2 x23 = *(const float2*)(r0p+2);
            float2 y01 = *(const float2*)r1p;
            float2 y23 = *(const float2*)(r1p+2);
            a0 = fmaf(wa[kh*3+0], x01.x, a0); a0 = fmaf(wa[kh*3+1], x01.y, a0); a0 = fmaf(wa[kh*3+2], x23.x, a0);
            a1 = fmaf(wa[kh*3+0], x01.y, a1); a1 = fmaf(wa[kh*3+1], x23.x, a1); a1 = fmaf(wa[kh*3+2], x23.y, a1);
            c0v = fmaf(wb[kh*3+0], y01.x, c0v); c0v = fmaf(wb[kh*3+1], y01.y, c0v); c0v = fmaf(wb[kh*3+2], y23.x, c0v);
            c1v = fmaf(wb[kh*3+0], y01.y, c1v); c1v = fmaf(wb[kh*3+1], y23.x, c1v); c1v = fmaf(wb[kh*3+2], y23.y, c1v);
        }
        float p0v = a0 * c0v, p1v = a1 * c1v;
        g_t[b][j][(r0+orow)*128 + cp] = pack_bf16(p0v, p1v);
        lsum += p0v + p1v;
    }
    #pragma unroll
    for (int off = 16; off > 0; off >>= 1) lsum += __shfl_down_sync(0xffffffffu, lsum, off);
    if ((t & 31) == 0) redbuf[t >> 5] = lsum;
    __syncthreads();
    if (t == 0) {
        float tot = 0.f;
        #pragma unroll
        for (int i = 0; i < 8; i++) tot += redbuf[i];
        g_poolpart[b][j][blockIdx.x] = tot;
    }
}

// ---------------- K4 v2: fused tail via wmma, 128-pixel tiles, bf16 Dst, y in regs ----------------
#define TP4 128
#define D_LD 136   // bf16 stride for xb/Dst
#define D_LDU 68   // u32 stride

__global__ __launch_bounds__(256, 2) void k4_final(
    const float* __restrict__ inp,
    const float* __restrict__ bsca,
    const float* __restrict__ b3, const float* __restrict__ b4, const float* __restrict__ b5,
    const float* __restrict__ ln2w, const float* __restrict__ ln2b,
    const float* __restrict__ beta, const float* __restrict__ gamma,
    float* __restrict__ out)
{
    extern __shared__ char smraw[];
    __nv_bfloat16* w3s = (__nv_bfloat16*)smraw;    // [64][72]
    __nv_bfloat16* w4s = w3s + CC*W_LD;            // [128][72]
    __nv_bfloat16* w5s = w4s + DWC*W_LD;           // [64][72]
    __nv_bfloat16* xb  = w5s + CC*W_LD;            // [64][136]  MMA B operand
    __nv_bfloat16* Dst = xb + CC*D_LD;             // [128][136] MMA outputs (bf16)
    float* stg  = (float*)(Dst + DWC*D_LD);        // [8][256]
    float* mu   = stg + 8*256;                     // 128
    float* rstd = mu + 128;                        // 128
    float* redS = rstd + 128;                      // 256
    float* redQ = redS + 256;                      // 256
    float* scas = redQ + 256;                      // 64
    float* pl   = scas + 64;                       // 64
    float* sb3  = pl + 64;                         // 64
    float* sb4  = sb3 + 64;                        // 128
    float* sb5  = sb4 + 128;                       // 64
    float* sbeta = sb5 + 64;                       // 64
    float* sgamma = sbeta + 64;                    // 64
    float* slnw = sgamma + 64;                     // 64
    float* slnb = slnw + 64;                       // 64

    int b = blockIdx.y;
    int pixbase = blockIdx.x * TP4;
    int t = threadIdx.x;
    int w = t >> 5, lane = t & 31;
    int px = t & 127, h = t >> 7;   // elementwise map: pixel px, channel half h

    u32* w3u = (u32*)w3s; u32* w4u = (u32*)w4s; u32* w5u = (u32*)w5s;
    u32* xbu = (u32*)xb;  u32* dstu = (u32*)Dst;

    // stage weights (bf16 pairs) + constants
    for (int idx = t; idx < CC*32; idx += 256) {
        int o = idx >> 5, p = idx & 31;
        w3u[o*36+p] = g_w3b[b][o][p];
        w5u[o*36+p] = g_w5b[b][o][p];
    }
    for (int idx = t; idx < DWC*32; idx += 256) {
        int o = idx >> 5, p = idx & 31;
        w4u[o*36+p] = g_w4b[b][o][p];
    }
    if (t < 64) {
        float s = 0.f;
        #pragma unroll
        for (int p = 0; p < 32; p++) s += g_poolpart[b][t][p];
        pl[t] = s;
        sb3[t] = b3[t]; sb5[t] = b5[t];
        sbeta[t] = beta[t]; sgamma[t] = gamma[t];
        slnw[t] = ln2w[t]; slnb[t] = ln2b[t];
    }
    if (t < 128) sb4[t] = b4[t];
    __syncthreads();

    if (t < 64) {
        float acc = 0.f;
        #pragma unroll 8
        for (int i = 0; i < CC; i++) acc += g_wscaf[b][t][i] * pl[i];
        scas[t] = bsca[t] + acc * (1.f/HWP);
    }
    __syncthreads();

    // xb = bf16(t * sca), pair-wise: 64 channels x 64 pixel-pairs
    int prb = pixbase >> 1;
    for (int idx = t; idx < CC*64; idx += 256) {
        int c = idx >> 6, pr = idx & 63;
        float2 f = bf16pair_to_f2(g_t[b][c][prb + pr]);
        float sc = scas[c];
        xbu[c*D_LDU + pr] = pack_bf16(f.x*sc, f.y*sc);
    }
    __syncthreads();

    float* stgw = stg + w*256;

    // ---- conv3 (64->64): warp w -> ocRow r=w&3, pixTiles (w>>2)*4 .. +3
    {
        int r = w & 3;
        wmma::fragment<wmma::matrix_a, 16, 16, 16, __nv_bfloat16, wmma::row_major> af[4];
        #pragma unroll
        for (int kt = 0; kt < 4; kt++)
            wmma::load_matrix_sync(af[kt], w3s + (r*16)*W_LD + kt*16, W_LD);
        #pragma unroll
        for (int pi = 0; pi < 4; pi++) {
            int pc = (w >> 2)*4 + pi;
            wmma::fragment<wmma::accumulator, 16, 16, 16, float> acc;
            wmma::fill_fragment(acc, 0.f);
            #pragma unroll
            for (int kt = 0; kt < 4; kt++) {
                wmma::fragment<wmma::matrix_b, 16, 16, 16, __nv_bfloat16, wmma::row_major> bf;
                wmma::load_matrix_sync(bf, xb + (kt*16)*D_LD + pc*16, D_LD);
                wmma::mma_sync(acc, af[kt], bf, acc);
            }
            wmma::store_matrix_sync(stgw, acc, 16, wmma::mem_row_major);
            __syncwarp();
            #pragma unroll
            for (int j = 0; j < 4; j++) {
                int lin = lane*4 + j;
                int row = lin >> 3, pr = lin & 7;
                dstu[(r*16+row)*D_LDU + pc*8 + pr] =
                    pack_bf16(stgw[row*16 + 2*pr], stgw[row*16 + 2*pr + 1]);
            }
            __syncwarp();
        }
    }
    __syncthreads();

    // y = inp + (conv3 + b3) * beta   (y kept in registers; LN2 partials)
    float yreg[32];
    {
        const float* IP = inp + ((size_t)(b*CC + h*32))*HWP + pixbase + px;
        float s = 0.f, sq = 0.f;
        #pragma unroll
        for (int i = 0; i < 32; i++) {
            int c = h*32 + i;
            float d = __bfloat162float(Dst[c*D_LD + px]);
            float yv = IP[(size_t)i*HWP] + (d + sb3[c]) * sbeta[c];
            yreg[i] = yv; s += yv; sq += yv*yv;
        }
        redS[h*128 + px] = s; redQ[h*128 + px] = sq;
    }
    __syncthreads();
    if (t < 128) {
        float s  = redS[t] + redS[128+t];
        float sq = redQ[t] + redQ[128+t];
        float m = s * (1.f/CC);
        float var = sq * (1.f/CC) - m*m;
        mu[t] = m; rstd[t] = rsqrtf(var + EPSF);
    }
    __syncthreads();

    // xb = bf16(ln2(y))  (single-bf16 stores, coalesced px across warp)
    {
        float m = mu[px], rs = rstd[px];
        #pragma unroll
        for (int i = 0; i < 32; i++) {
            int c = h*32 + i;
            xb[c*D_LD + px] = __float2bfloat16((yreg[i]-m)*rs*slnw[c] + slnb[c]);
        }
    }
    __syncthreads();

    // ---- conv4 (64->128): warp w -> ocRow w, pixTiles 0..7
    {
        wmma::fragment<wmma::matrix_a, 16, 16, 16, __nv_bfloat16, wmma::row_major> af[4];
        #pragma unroll
        for (int kt = 0; kt < 4; kt++)
            wmma::load_matrix_sync(af[kt], w4s + (w*16)*W_LD + kt*16, W_LD);
        for (int pc = 0; pc < 8; pc++) {
            wmma::fragment<wmma::accumulator, 16, 16, 16, float> acc;
            wmma::fill_fragment(acc, 0.f);
            #pragma unroll
            for (int kt = 0; kt < 4; kt++) {
                wmma::fragment<wmma::matrix_b, 16, 16, 16, __nv_bfloat16, wmma::row_major> bf;
                wmma::load_matrix_sync(bf, xb + (kt*16)*D_LD + pc*16, D_LD);
                wmma::mma_sync(acc, af[kt], bf, acc);
            }
            wmma::store_matrix_sync(stgw, acc, 16, wmma::mem_row_major);
            __syncwarp();
            #pragma unroll
            for (int j = 0; j < 4; j++) {
                int lin = lane*4 + j;
                int row = lin >> 3, pr = lin & 7;
                dstu[(w*16+row)*D_LDU + pc*8 + pr] =
                    pack_bf16(stgw[row*16 + 2*pr], stgw[row*16 + 2*pr + 1]);
            }
            __syncwarp();
        }
    }
    __syncthreads();

    // SimpleGate -> xb (pair-wise)
    for (int idx = t; idx < CC*64; idx += 256) {
        int c = idx >> 6, pr = idx & 63;
        float2 a = bf16pair_to_f2(dstu[c*D_LDU + pr]);
        float2 d2 = bf16pair_to_f2(dstu[(c+CC)*D_LDU + pr]);
        float bA = sb4[c], bB = sb4[c+CC];
        xbu[c*D_LDU + pr] = pack_bf16((a.x+bA)*(d2.x+bB), (a.y+bA)*(d2.y+bB));
    }
    __syncthreads();

    // ---- conv5 (64->64): like conv3
    {
        int r = w & 3;
        wmma::fragment<wmma::matrix_a, 16, 16, 16, __nv_bfloat16, wmma::row_major> af[4];
        #pragma unroll
        for (int kt = 0; kt < 4; kt++)
            wmma::load_matrix_sync(af[kt], w5s + (r*16)*W_LD + kt*16, W_LD);
        #pragma unroll
        for (int pi = 0; pi < 4; pi++) {
            int pc = (w >> 2)*4 + pi;
            wmma::fragment<wmma::accumulator, 16, 16, 16, float> acc;
            wmma::fill_fragment(acc, 0.f);
            #pragma unroll
            for (int kt = 0; kt < 4; kt++) {
                wmma::fragment<wmma::matrix_b, 16, 16, 16, __nv_bfloat16, wmma::row_major> bf;
                wmma::load_matrix_sync(bf, xb + (kt*16)*D_LD + pc*16, D_LD);
                wmma::mma_sync(acc, af[kt], bf, acc);
            }
            wmma::store_matrix_sync(stgw, acc, 16, wmma::mem_row_major);
            __syncwarp();
            #pragma unroll
            for (int j = 0; j < 4; j++) {
                int lin = lane*4 + j;
                int row = lin >> 3, pr = lin & 7;
                dstu[(r*16+row)*D_LDU + pc*8 + pr] =
                    pack_bf16(stgw[row*16 + 2*pr], stgw[row*16 + 2*pr + 1]);
            }
            __syncwarp();
        }
    }
    __syncthreads();

    // out = y + (conv5 + b5) * gamma
    {
        float* OP = out + ((size_t)(b*CC + h*32))*HWP + pixbase + px;
        #pragma unroll
        for (int i = 0; i < 32; i++) {
            int c = h*32 + i;
            float d = __bfloat162float(Dst[c*D_LD + px]);
            OP[(size_t)i*HWP] = yreg[i] + (d + sb5[c]) * sgamma[c];
        }
    }
}

// ---------------- launch ----------------
extern "C" void kernel_launch(void* const* d_in, const int* in_sizes, int n_in,
                              void* d_out, int out_size)
{
    const float* inp   = (const float*)d_in[0];
    const float* probs = (const float*)d_in[1];
    const float* ln1w  = (const float*)d_in[2];
    const float* ln1b  = (const float*)d_in[3];
    const float* ln2w  = (const float*)d_in[4];
    const float* ln2b  = (const float*)d_in[5];
    const float* w1    = (const float*)d_in[6];
    const float* b1    = (const float*)d_in[7];
    const float* la1   = (const float*)d_in[8];
    const float* lb1   = (const float*)d_in[9];
    const float* w2    = (const float*)d_in[10];
    const float* b2    = (const float*)d_in[11];
    const float* la2   = (const float*)d_in[12];
    const float* lb2   = (const float*)d_in[13];
    const float* wsca  = (const float*)d_in[14];
    const float* bsca  = (const float*)d_in[15];
    const float* la_s  = (const float*)d_in[16];
    const float* lb_s  = (const float*)d_in[17];
    const float* w3    = (const float*)d_in[18];
    const float* b3    = (const float*)d_in[19];
    const float* la3   = (const float*)d_in[20];
    const float* lb3   = (const float*)d_in[21];
    const float* w4    = (const float*)d_in[22];
    const float* b4    = (const float*)d_in[23];
    const float* la4   = (const float*)d_in[24];
    const float* lb4   = (const float*)d_in[25];
    const float* w5    = (const float*)d_in[26];
    const float* b5    = (const float*)d_in[27];
    const float* la5   = (const float*)d_in[28];
    const float* lb5   = (const float*)d_in[29];
    const float* beta  = (const float*)d_in[30];
    const float* gamma = (const float*)d_in[31];
    float* out = (float*)d_out;

    const int smem1 = DWC*W_LD*2 + CC*XB_LD*2 + 8*256*4
                    + (256+256+128+128+128+64+64)*4;
    const int smem4 = (CC*W_LD + DWC*W_LD + CC*W_LD)*2
                    + CC*D_LD*2 + DWC*D_LD*2 + 8*256*4
                    + (128+128+256+256+64+64+64+128+64+64+64+64+64)*4;  // 102912
    cudaFuncSetAttribute(k1_ln_conv1, cudaFuncAttributeMaxDynamicSharedMemorySize, smem1);
    cudaFuncSetAttribute(k4_final,    cudaFuncAttributeMaxDynamicSharedMemorySize, smem4);

    k0_weights<<<BB, 256>>>(probs, w1, la1, lb1, w3, la3, lb3,
                            w4, la4, lb4, w5, la5, lb5, wsca, la_s, lb_s);
    k1_ln_conv1<<<dim3(HWP/128, BB), 256, smem1>>>(inp, ln1w, ln1b, b1);
    k2_dw_gate_pool<<<dim3(HH/8, CC, BB), 256>>>(probs, w2, la2, lb2, b2);
    k4_final<<<dim3(HWP/TP4, BB), 256, smem4>>>(inp, bsca, b3, b4, b5,
                                                ln2w, ln2b, beta, gamma, out);
}